// round 2
// baseline (speedup 1.0000x reference)
#include <cuda_runtime.h>
#include <cstdint>

// ---------------- problem constants ----------------
#define H 128
#define W 128
#define C 256
#define O 256
#define KH 3
#define KW 3
#define OH 126
#define OW 126

#define NNZ_CAP 2048

// ---------------- tiling ----------------
#define TH 4            // output rows per block
#define TW 32           // output cols per block
#define ROWS (TH + 2)   // input rows needed
#define XT (TW + 2)     // input cols needed
#define XP 34           // x-pitch for input smem
#define TWP 33          // x-pitch for output staging (odd -> conflict-free transpose)

#define S_IN_FLOATS (ROWS * C * XP)                 // 52224 floats = 208896 B
#define SMEM_BYTES  (S_IN_FLOATS * 4 + NNZ_CAP * 8) // + csr 16384 B = 225280 B

// ---------------- device scratch (no allocations allowed) ----------------
__device__ int   g_off[O + 1];
__device__ uint2 g_csr[NNZ_CAP];   // .x = (dy<<16)|(dx<<8)|c_eff ; .y = float bits

// ============================================================
// Prep: build CSR grouped by output channel, applying the
// (kh,kw,C) vs (C,kh,kw) flattening remap from the reference.
// weight_indices is INT32 (JAX x64 disabled demotes the astype(int64)).
// ============================================================
__global__ void __launch_bounds__(1024)
prep_kernel(const int* __restrict__ wi,
            const float* __restrict__ wv, int nnz)
{
    __shared__ int s_cnt[O];
    __shared__ int s_cur[O];
    __shared__ int s_off[O + 1];
    int tid = threadIdx.x;

    if (tid < O) { s_cnt[tid] = 0; s_cur[tid] = 0; }
    __syncthreads();

    for (int i = tid; i < nnz; i += 1024) {
        int o = wi[4 * i + 0];
        atomicAdd(&s_cnt[o], 1);
    }
    __syncthreads();

    // exclusive scan of 256 counts by warp 0 (8 per lane + warp scan)
    if (tid < 32) {
        int base = tid * 8;
        int v[8], loc[8], run = 0;
#pragma unroll
        for (int j = 0; j < 8; j++) { v[j] = s_cnt[base + j]; loc[j] = run; run += v[j]; }
        int incl = run;
#pragma unroll
        for (int d = 1; d < 32; d <<= 1) {
            int n = __shfl_up_sync(0xffffffffu, incl, d);
            if (tid >= d) incl += n;
        }
        int excl = incl - run;
#pragma unroll
        for (int j = 0; j < 8; j++) s_off[base + j] = excl + loc[j];
        if (tid == 31) s_off[O] = incl;
    }
    __syncthreads();

    if (tid < O + 1) g_off[tid] = s_off[tid];

    for (int i = tid; i < nnz; i += 1024) {
        int o  = wi[4 * i + 0];
        int ih = wi[4 * i + 1];
        int iw = wi[4 * i + 2];
        int ic = wi[4 * i + 3];
        // reference flattening mismatch remap:
        int k  = ih * (KW * C) + iw * C + ic;   // flat index in W.reshape(O,-1)
        int ce = k / 9;                          // effective input channel
        int t  = k - 9 * ce;
        int dy = t / 3;
        int dx = t - 3 * dy;
        int pos = s_off[o] + atomicAdd(&s_cur[o], 1);
        uint2 e;
        e.x = ((unsigned)dy << 16) | ((unsigned)dx << 8) | (unsigned)ce;
        e.y = __float_as_uint(wv[i]);
        g_csr[pos] = e;
    }
}

// ============================================================
// Main kernel: one CTA = [TH x TW] output tile, all 256 o-channels.
//   phase 1: stage input tile transposed to [row][c][x] + CSR in smem
//   phase 2: warp w handles o in [16w,16w+16); lane = x; 64 accs/thread
//   phase 3: transpose via smem (reusing input region) -> coalesced STG
// ============================================================
__global__ void __launch_bounds__(512, 1)
sparse_conv_kernel(const float* __restrict__ in,
                   float* __restrict__ out, int nnz)
{
    extern __shared__ float smem[];
    float* s_in  = smem;                                   // 52224 floats
    uint2* s_csr = (uint2*)(smem + S_IN_FLOATS);           // 2048 entries
    __shared__ int s_off[O + 1];

    const int tid    = threadIdx.x;
    const int warpId = tid >> 5;
    const int lane   = tid & 31;

    const int x0 = blockIdx.x * TW;
    const int y0 = blockIdx.y * TH;
    const int bz = blockIdx.z;

    // ---- phase 1: stage metadata + input tile ----
    if (tid < O + 1) s_off[tid] = g_off[tid];
    for (int i = tid; i < nnz; i += 512) s_csr[i] = g_csr[i];

    // warp-granular: each task = 32 consecutive channels of one (row,x) pixel
    for (int idx = warpId; idx < ROWS * XT * (C / 32); idx += 16) {
        int seg = idx >> 3;             // pixel index 0..203
        int cg  = idx & 7;
        int rr  = seg / XT;
        int xx  = seg - rr * XT;
        int c   = cg * 32 + lane;
        int iy  = y0 + rr;
        int ix  = x0 + xx;
        float v = 0.0f;
        if (iy < H && ix < W)
            v = in[(((size_t)bz * H + iy) * W + ix) * C + c];
        s_in[(rr * C + c) * XP + xx] = v;
    }
    __syncthreads();

    // ---- phase 2: gather-accumulate ----
    const int oBase = warpId * 16;
    float acc[16][TH];
#pragma unroll
    for (int oo = 0; oo < 16; oo++)
#pragma unroll
        for (int r = 0; r < TH; r++) acc[oo][r] = 0.0f;

#pragma unroll
    for (int oo = 0; oo < 16; oo++) {
        const int o  = oBase + oo;
        const int k0 = s_off[o];
        const int k1 = s_off[o + 1];
        for (int k = k0; k < k1; k++) {
            uint2 e = s_csr[k];                      // uniform address: broadcast
            float v = __uint_as_float(e.y);
            int dy  = (int)(e.x >> 16);
            int dx  = (int)((e.x >> 8) & 0xFF);
            int ic  = (int)(e.x & 0xFF);
            const float* p = s_in + (dy * C + ic) * XP + dx + lane;  // conflict-free
#pragma unroll
            for (int r = 0; r < TH; r++)
                acc[oo][r] += v * p[r * C * XP];
        }
    }
    __syncthreads();   // s_in dead -> safe to reuse

    // ---- phase 3: transpose-stage and coalesced store ----
    float* s_out = s_in;  // layout [r][o][x], pitch TWP=33
#pragma unroll
    for (int oo = 0; oo < 16; oo++) {
        int o = oBase + oo;
#pragma unroll
        for (int r = 0; r < TH; r++)
            s_out[(r * O + o) * TWP + lane] = acc[oo][r];   // conflict-free STS
    }
    __syncthreads();

    const int och = tid & 255;
    for (int p = tid >> 8; p < TH * TW; p += 2) {
        int r   = p >> 5;
        int xx  = p & 31;
        int gy  = y0 + r;
        int gx  = x0 + xx;
        if (gy < OH && gx < OW)
            out[(((size_t)bz * OH + gy) * OW + gx) * O + och] =
                s_out[(r * O + och) * TWP + xx];            // conflict-free LDS, coalesced STG
    }
}

// ============================================================
extern "C" void kernel_launch(void* const* d_in, const int* in_sizes, int n_in,
                              void* d_out, int out_size)
{
    const float* in  = (const float*)d_in[0];
    const int*   wi  = (const int*)d_in[1];
    const float* wv  = (const float*)d_in[2];
    float*       out = (float*)d_out;

    int nnz = in_sizes[2];
    if (nnz > NNZ_CAP) nnz = NNZ_CAP;
    int B = in_sizes[0] / (H * W * C);

    prep_kernel<<<1, 1024>>>(wi, wv, nnz);

    cudaFuncSetAttribute(sparse_conv_kernel,
                         cudaFuncAttributeMaxDynamicSharedMemorySize, SMEM_BYTES);

    dim3 grid((OW + TW - 1) / TW, (OH + TH - 1) / TH, B);
    sparse_conv_kernel<<<grid, 512, SMEM_BYTES>>>(in, out, nnz);
}

// round 3
// speedup vs baseline: 1.3659x; 1.3659x over previous
#include <cuda_runtime.h>
#include <cstdint>

// ---------------- problem constants ----------------
#define H 128
#define W 128
#define C 256
#define O 256
#define KH 3
#define KW 3
#define OH 126
#define OW 126

#define NNZ_CAP 2048
#define NNZ_PAD 2304          // 2048 + 256 (each bucket padded to even)

// ---------------- tiling ----------------
#define TH 4            // output rows per block
#define TW 32           // output cols per block
#define ROWS (TH + 2)   // input rows needed
#define XT (TW + 2)     // input cols needed
#define XP 34           // x-pitch for input smem (2-way STS conflict, reads conflict-free)
#define TWP 33          // x-pitch for output staging (conflict-free transpose)
#define RPITCH (C * XP) // row pitch in s_in

#define S_IN_FLOATS (ROWS * C * XP)                  // 52224 floats = 208896 B
#define SMEM_BYTES  (S_IN_FLOATS * 4 + NNZ_PAD * 8)  // 208896 + 18432 = 227328 B

// ---------------- device scratch ----------------
__device__ int   g_off[O + 1];
__device__ uint4 g_csr4[NNZ_PAD / 2];   // pairs of {off,valbits}

// ============================================================
// Prep: build CSR grouped by o-channel, remapping the reference's
// (kh,kw,C)-vs-(C,kh,kw) flatten mismatch, storing the FINAL smem
// word offset per entry, with each bucket zero-padded to even size.
// weight_indices is int32 (JAX demotes the astype(int64)).
// ============================================================
__global__ void __launch_bounds__(1024)
prep_kernel(const int* __restrict__ wi,
            const float* __restrict__ wv, int nnz)
{
    __shared__ int s_cnt[O];
    __shared__ int s_cur[O];
    __shared__ int s_off[O + 1];
    int tid = threadIdx.x;

    if (tid < O) { s_cnt[tid] = 0; s_cur[tid] = 0; }
    __syncthreads();

    for (int i = tid; i < nnz; i += 1024)
        atomicAdd(&s_cnt[wi[4 * i + 0]], 1);
    __syncthreads();

    // exclusive scan of 256 PADDED counts by warp 0
    if (tid < 32) {
        int base = tid * 8;
        int loc[8], run = 0;
#pragma unroll
        for (int j = 0; j < 8; j++) {
            int c = (s_cnt[base + j] + 1) & ~1;   // pad to even
            loc[j] = run; run += c;
        }
        int incl = run;
#pragma unroll
        for (int d = 1; d < 32; d <<= 1) {
            int n = __shfl_up_sync(0xffffffffu, incl, d);
            if (tid >= d) incl += n;
        }
        int excl = incl - run;
#pragma unroll
        for (int j = 0; j < 8; j++) s_off[base + j] = excl + loc[j];
        if (tid == 31) s_off[O] = incl;
    }
    __syncthreads();

    if (tid < O + 1) g_off[tid] = s_off[tid];

    // zero-fill all (padded) slots, then scatter real entries
    uint2* csr = (uint2*)g_csr4;
    for (int i = tid; i < NNZ_PAD; i += 1024) csr[i] = make_uint2(0u, 0u);
    __syncthreads();

    for (int i = tid; i < nnz; i += 1024) {
        int o  = wi[4 * i + 0];
        int ih = wi[4 * i + 1];
        int iw = wi[4 * i + 2];
        int ic = wi[4 * i + 3];
        int k  = ih * (KW * C) + iw * C + ic;    // flat idx in W.reshape(O,-1)
        int ce = k / 9;                           // effective input channel
        int t  = k - 9 * ce;
        int dy = t / 3;
        int dx = t - 3 * dy;
        int off = (dy * C + ce) * XP + dx;        // final smem word offset
        int pos = s_off[o] + atomicAdd(&s_cur[o], 1);
        csr[pos] = make_uint2((unsigned)off, __float_as_uint(wv[i]));
    }
}

// ============================================================
// Main kernel: 1024 threads. CTA = [TH x TW] tile, all 256 o.
//   phase 1: stage input [row][c][x] + CSR into smem
//   phase 2: warp w -> o in [8w, 8w+8); lane = x; 32 accs/thread
//            CSR consumed 2 entries per LDS.128 (buckets even-padded)
//   phase 3: transpose via smem reuse -> coalesced STG
// ============================================================
__global__ void __launch_bounds__(1024, 1)
sparse_conv_kernel(const float* __restrict__ in,
                   float* __restrict__ out)
{
    extern __shared__ float smem[];
    float* s_in  = smem;                              // 52224 floats
    uint2* s_csr = (uint2*)(smem + S_IN_FLOATS);      // 2304 entries
    __shared__ int s_off[O + 1];

    const int tid    = threadIdx.x;
    const int warpId = tid >> 5;
    const int lane   = tid & 31;

    const int x0 = blockIdx.x * TW;
    const int y0 = blockIdx.y * TH;
    const int bz = blockIdx.z;

    // ---- phase 1: stage metadata + CSR + input tile ----
    if (tid < O + 1) s_off[tid] = g_off[tid];
    {
        uint4* d = (uint4*)s_csr;
        for (int i = tid; i < NNZ_PAD / 2; i += 1024) d[i] = g_csr4[i];
    }
    // each task = 32 consecutive channels of one (row,x) pixel (LDG.32, 128B/warp)
    for (int idx = warpId; idx < ROWS * XT * (C / 32); idx += 32) {
        int seg = idx >> 3;             // pixel 0..203
        int cg  = idx & 7;
        int rr  = seg / XT;
        int xx  = seg - rr * XT;
        int c   = cg * 32 + lane;
        int iy  = y0 + rr;
        int ix  = x0 + xx;
        float v = 0.0f;
        if (iy < H && ix < W)
            v = in[(((size_t)bz * H + iy) * W + ix) * C + c];
        s_in[(rr * C + c) * XP + xx] = v;
    }
    __syncthreads();

    // ---- phase 2: gather-accumulate, 8 o per warp ----
    const int oBase = warpId * 8;
    float acc[8][TH];
#pragma unroll
    for (int oo = 0; oo < 8; oo++)
#pragma unroll
        for (int r = 0; r < TH; r++) acc[oo][r] = 0.0f;

#pragma unroll
    for (int oo = 0; oo < 8; oo++) {
        const int k0 = s_off[oBase + oo];
        const int k1 = s_off[oBase + oo + 1];
#pragma unroll 2
        for (int k = k0; k < k1; k += 2) {
            uint4 e = *(const uint4*)(s_csr + k);   // 2 entries, 16B-aligned
            const float* a0 = s_in + e.x + lane;
            const float* a1 = s_in + e.z + lane;
            float v0 = __uint_as_float(e.y);
            float v1 = __uint_as_float(e.w);
#pragma unroll
            for (int r = 0; r < TH; r++) acc[oo][r] += v0 * a0[r * RPITCH];
#pragma unroll
            for (int r = 0; r < TH; r++) acc[oo][r] += v1 * a1[r * RPITCH];
        }
    }
    __syncthreads();   // s_in dead -> safe to reuse

    // ---- phase 3: transpose-stage and coalesced store ----
    float* s_out = s_in;  // layout [r][o][x], pitch TWP=33 (33792 floats)
#pragma unroll
    for (int oo = 0; oo < 8; oo++) {
        int o = oBase + oo;
#pragma unroll
        for (int r = 0; r < TH; r++)
            s_out[(r * O + o) * TWP + lane] = acc[oo][r];
    }
    __syncthreads();

    const int och = tid & 255;
    for (int p = tid >> 8; p < TH * TW; p += 4) {
        int r  = p >> 5;
        int xx = p & 31;
        int gy = y0 + r;
        int gx = x0 + xx;
        if (gy < OH && gx < OW)
            out[(((size_t)bz * OH + gy) * OW + gx) * O + och] =
                s_out[(r * O + och) * TWP + xx];
    }
}

// ============================================================
extern "C" void kernel_launch(void* const* d_in, const int* in_sizes, int n_in,
                              void* d_out, int out_size)
{
    const float* in  = (const float*)d_in[0];
    const int*   wi  = (const int*)d_in[1];
    const float* wv  = (const float*)d_in[2];
    float*       out = (float*)d_out;

    int nnz = in_sizes[2];
    if (nnz > NNZ_CAP) nnz = NNZ_CAP;
    int B = in_sizes[0] / (H * W * C);

    prep_kernel<<<1, 1024>>>(wi, wv, nnz);

    cudaFuncSetAttribute(sparse_conv_kernel,
                         cudaFuncAttributeMaxDynamicSharedMemorySize, SMEM_BYTES);

    dim3 grid((OW + TW - 1) / TW, (OH + TH - 1) / TH, B);
    sparse_conv_kernel<<<grid, 1024, SMEM_BYTES>>>(in, out);
}

// round 4
// speedup vs baseline: 1.9262x; 1.4102x over previous
#include <cuda_runtime.h>
#include <cstdint>

// ---------------- problem constants ----------------
#define H 128
#define W 128
#define C 256
#define O 256
#define KH 3
#define KW 3
#define OH 126
#define OW 126

#define NNZ_CAP 2048
#define NNZ_PAD 2304          // 2048 + 256 (each bucket padded to even)

// ---------------- tiling ----------------
#define TH 4            // output rows per block
#define TW 32           // output cols per block
#define ROWS (TH + 2)   // input rows needed
#define XT (TW + 2)     // input cols needed
#define XP 34           // x-pitch for input smem
#define TWP 33          // x-pitch for output staging (conflict-free transpose)
#define RPITCH (C * XP) // row pitch in s_in (floats)

#define S_IN_FLOATS (ROWS * C * XP)                  // 52224 floats = 208896 B
#define SMEM_BYTES  (S_IN_FLOATS * 4 + NNZ_PAD * 8)  // 227328 B dynamic

// ---------------- device scratch ----------------
__device__ int   g_off[O + 1];
__device__ uint4 g_csr4[NNZ_PAD / 2];   // pairs of {off,valbits}

// ============================================================
// Prep: CSR grouped by o-channel, remapping the reference's
// (kh,kw,C)-vs-(C,kh,kw) flatten mismatch; stores the FINAL smem
// word offset per entry; buckets zero-padded to even length.
// weight_indices is int32 (JAX demotes the astype(int64)).
// ============================================================
__global__ void __launch_bounds__(1024)
prep_kernel(const int* __restrict__ wi,
            const float* __restrict__ wv, int nnz)
{
    __shared__ int s_cnt[O];
    __shared__ int s_cur[O];
    __shared__ int s_off[O + 1];
    int tid = threadIdx.x;

    if (tid < O) { s_cnt[tid] = 0; s_cur[tid] = 0; }
    __syncthreads();

    for (int i = tid; i < nnz; i += 1024)
        atomicAdd(&s_cnt[wi[4 * i + 0]], 1);
    __syncthreads();

    if (tid < 32) {
        int base = tid * 8;
        int loc[8], run = 0;
#pragma unroll
        for (int j = 0; j < 8; j++) {
            int c = (s_cnt[base + j] + 1) & ~1;   // pad to even
            loc[j] = run; run += c;
        }
        int incl = run;
#pragma unroll
        for (int d = 1; d < 32; d <<= 1) {
            int n = __shfl_up_sync(0xffffffffu, incl, d);
            if (tid >= d) incl += n;
        }
        int excl = incl - run;
#pragma unroll
        for (int j = 0; j < 8; j++) s_off[base + j] = excl + loc[j];
        if (tid == 31) s_off[O] = incl;
    }
    __syncthreads();

    if (tid < O + 1) g_off[tid] = s_off[tid];

    uint2* csr = (uint2*)g_csr4;
    for (int i = tid; i < NNZ_PAD; i += 1024) csr[i] = make_uint2(0u, 0u);
    __syncthreads();

    for (int i = tid; i < nnz; i += 1024) {
        int o  = wi[4 * i + 0];
        int ih = wi[4 * i + 1];
        int iw = wi[4 * i + 2];
        int ic = wi[4 * i + 3];
        int k  = ih * (KW * C) + iw * C + ic;    // flat idx in W.reshape(O,-1)
        int ce = k / 9;                           // effective input channel
        int t  = k - 9 * ce;
        int dy = t / 3;
        int dx = t - 3 * dy;
        int off = (dy * C + ce) * XP + dx;        // final smem word offset
        int pos = s_off[o] + atomicAdd(&s_cur[o], 1);
        csr[pos] = make_uint2((unsigned)off, __float_as_uint(wv[i]));
    }
}

// ============================================================
// Main kernel: 1024 threads, CTA = [TH x TW] tile, all 256 o.
// ============================================================
__global__ void __launch_bounds__(1024, 1)
sparse_conv_kernel(const float* __restrict__ in,
                   float* __restrict__ out)
{
    extern __shared__ float smem[];
    float* s_in  = smem;                              // 52224 floats
    uint2* s_csr = (uint2*)(smem + S_IN_FLOATS);      // 2304 entries
    __shared__ int s_off[O + 1];

    const int tid    = threadIdx.x;
    const int warpId = tid >> 5;
    const int lane   = tid & 31;

    const int x0 = blockIdx.x * TW;
    const int y0 = blockIdx.y * TH;
    const int bz = blockIdx.z;

    // ---- phase 1a: metadata + CSR into smem ----
    if (tid < O + 1) s_off[tid] = g_off[tid];
    {
        uint4* d = (uint4*)s_csr;
        for (int i = tid; i < NNZ_PAD / 2; i += 1024) d[i] = g_csr4[i];
    }

    // ---- phase 1b: stage input tile [row][c][x] ----
    // one pixel (rr,xx) per warp-iteration; 8 channel-groups with
    // immediate offsets (batched LDG -> batched STS).
#pragma unroll
    for (int t = 0; t < 7; t++) {
        int p = warpId + (t << 5);
        if (p < ROWS * XT) {
            int rr = p / XT;
            int xx = p - rr * XT;
            int iy = y0 + rr;
            int ix = x0 + xx;
            float* sb = s_in + (rr * C + lane) * XP + xx;
            if ((iy < H) && (ix < W)) {
                const float* gb = in + (((bz * H + iy) * W + ix) * C) + lane;
                float v[8];
#pragma unroll
                for (int cg = 0; cg < 8; cg++) v[cg] = gb[cg * 32];
#pragma unroll
                for (int cg = 0; cg < 8; cg++) sb[cg * 32 * XP] = v[cg];
            } else {
#pragma unroll
                for (int cg = 0; cg < 8; cg++) sb[cg * 32 * XP] = 0.0f;
            }
        }
    }
    __syncthreads();

    // ---- phase 2: gather-accumulate, 8 o per warp, lane = x ----
    const int oBase = warpId * 8;
    const float* s_in_lane = s_in + lane;
    float acc[8][TH];
#pragma unroll
    for (int oo = 0; oo < 8; oo++)
#pragma unroll
        for (int r = 0; r < TH; r++) acc[oo][r] = 0.0f;

#pragma unroll
    for (int oo = 0; oo < 8; oo++) {
        const int k0 = s_off[oBase + oo];
        const int k1 = s_off[oBase + oo + 1];
        for (int k = k0; k < k1; k += 2) {
            uint4 e = *(const uint4*)(s_csr + k);     // 2 entries, 16B aligned
            const float* a0 = s_in_lane + e.x;
            const float* a1 = s_in_lane + e.z;
            float v0 = __uint_as_float(e.y);
            float v1 = __uint_as_float(e.w);
#pragma unroll
            for (int r = 0; r < TH; r++) acc[oo][r] += v0 * a0[r * RPITCH];
#pragma unroll
            for (int r = 0; r < TH; r++) acc[oo][r] += v1 * a1[r * RPITCH];
        }
    }
    __syncthreads();   // s_in dead -> reuse

    // ---- phase 3: transpose-stage and coalesced store ----
    float* s_out = s_in;  // [r][o][x], pitch TWP=33
#pragma unroll
    for (int oo = 0; oo < 8; oo++) {
        int o = oBase + oo;
#pragma unroll
        for (int r = 0; r < TH; r++)
            s_out[(r * O + o) * TWP + lane] = acc[oo][r];
    }
    __syncthreads();

    const int och  = tid & 255;
    const int pgrp = tid >> 8;             // 0..3
    const int obase32 = ((bz * OH + y0) * OW + x0) * O + och;
#pragma unroll
    for (int i = 0; i < 32; i++) {
        int p  = pgrp + (i << 2);          // 0..127
        int r  = p >> 5;
        int xx = p & 31;
        int gy = y0 + r;
        int gx = x0 + xx;
        if (gy < OH && gx < OW)
            out[obase32 + (r * OW + xx) * O] =
                s_out[(r * O + och) * TWP + xx];
    }
}

// ============================================================
extern "C" void kernel_launch(void* const* d_in, const int* in_sizes, int n_in,
                              void* d_out, int out_size)
{
    const float* in  = (const float*)d_in[0];
    const int*   wi  = (const int*)d_in[1];
    const float* wv  = (const float*)d_in[2];
    float*       out = (float*)d_out;

    int nnz = in_sizes[2];
    if (nnz > NNZ_CAP) nnz = NNZ_CAP;
    int B = in_sizes[0] / (H * W * C);

    prep_kernel<<<1, 1024>>>(wi, wv, nnz);

    cudaFuncSetAttribute(sparse_conv_kernel,
                         cudaFuncAttributeMaxDynamicSharedMemorySize, SMEM_BYTES);

    dim3 grid((OW + TW - 1) / TW, (OH + TH - 1) / TH, B);
    sparse_conv_kernel<<<grid, 1024, SMEM_BYTES>>>(in, out);
}

// round 5
// speedup vs baseline: 1.9271x; 1.0005x over previous
#include <cuda_runtime.h>
#include <cstdint>

// ---------------- problem constants ----------------
#define H 128
#define W 128
#define C 256
#define O 256
#define KH 3
#define KW 3
#define OH 126
#define OW 126

#define NNZ_CAP 2048
#define NNZ_PAD 2304          // 2048 + 256 (each bucket padded to even)

// ---------------- tiling ----------------
#define TH 4            // output rows per block
#define TW 32           // output cols per block
#define ROWS (TH + 2)   // input rows needed
#define XT (TW + 2)     // input cols needed
#define XP 34           // x-pitch for input smem
#define TWP 33          // x-pitch for output staging (conflict-free transpose)
#define RPITCH (C * XP) // row pitch in s_in (floats)

#define S_IN_FLOATS (ROWS * C * XP)                  // 52224 floats = 208896 B
#define SMEM_BYTES  (S_IN_FLOATS * 4 + NNZ_PAD * 8)  // 227328 B dynamic

// ---------------- device scratch ----------------
__device__ int   g_off[O + 1];
__device__ uint4 g_csr4[NNZ_PAD / 2];   // pairs of {off,valbits}

// ============================================================
// Prep: CSR grouped by o-channel, remapping the reference's
// (kh,kw,C)-vs-(C,kh,kw) flatten mismatch; stores the FINAL smem
// word offset per entry; buckets zero-padded to even length.
// weight_indices is int32 (JAX demotes the astype(int64)).
// ============================================================
__global__ void __launch_bounds__(1024)
prep_kernel(const int* __restrict__ wi,
            const float* __restrict__ wv, int nnz)
{
    __shared__ int s_cnt[O];
    __shared__ int s_cur[O];
    __shared__ int s_off[O + 1];
    int tid = threadIdx.x;

    if (tid < O) { s_cnt[tid] = 0; s_cur[tid] = 0; }
    __syncthreads();

    for (int i = tid; i < nnz; i += 1024)
        atomicAdd(&s_cnt[wi[4 * i + 0]], 1);
    __syncthreads();

    if (tid < 32) {
        int base = tid * 8;
        int loc[8], run = 0;
#pragma unroll
        for (int j = 0; j < 8; j++) {
            int c = (s_cnt[base + j] + 1) & ~1;   // pad to even
            loc[j] = run; run += c;
        }
        int incl = run;
#pragma unroll
        for (int d = 1; d < 32; d <<= 1) {
            int n = __shfl_up_sync(0xffffffffu, incl, d);
            if (tid >= d) incl += n;
        }
        int excl = incl - run;
#pragma unroll
        for (int j = 0; j < 8; j++) s_off[base + j] = excl + loc[j];
        if (tid == 31) s_off[O] = incl;
    }
    __syncthreads();

    if (tid < O + 1) g_off[tid] = s_off[tid];

    uint2* csr = (uint2*)g_csr4;
    // zero the (at most one) pad slot per bucket
    if (tid < O) {
        int cnt = s_cnt[tid];
        if (cnt & 1) csr[s_off[tid] + cnt] = make_uint2(0u, 0u);
    }

    for (int i = tid; i < nnz; i += 1024) {
        int o  = wi[4 * i + 0];
        int ih = wi[4 * i + 1];
        int iw = wi[4 * i + 2];
        int ic = wi[4 * i + 3];
        int k  = ih * (KW * C) + iw * C + ic;    // flat idx in W.reshape(O,-1)
        int ce = k / 9;                           // effective input channel
        int t  = k - 9 * ce;
        int dy = t / 3;
        int dx = t - 3 * dy;
        int off = (dy * C + ce) * XP + dx;        // final smem word offset
        int pos = s_off[o] + atomicAdd(&s_cur[o], 1);
        csr[pos] = make_uint2((unsigned)off, __float_as_uint(wv[i]));
    }
}

// ============================================================
// Main kernel: 1024 threads, CTA = [TH x TW] tile, all 256 o.
// ============================================================
__global__ void __launch_bounds__(1024, 1)
sparse_conv_kernel(const float* __restrict__ in,
                   float* __restrict__ out)
{
    extern __shared__ float smem[];
    float* s_in  = smem;                              // 52224 floats
    uint2* s_csr = (uint2*)(smem + S_IN_FLOATS);      // 2304 entries
    __shared__ int s_off[O + 1];

    const int tid    = threadIdx.x;
    const int warpId = tid >> 5;
    const int lane   = tid & 31;

    const int x0 = blockIdx.x * TW;
    const int y0 = blockIdx.y * TH;
    const int bz = blockIdx.z;

    // ---- phase 1a: metadata + CSR into smem ----
    if (tid < O + 1) s_off[tid] = g_off[tid];
    {
        uint4* d = (uint4*)s_csr;
        for (int i = tid; i < NNZ_PAD / 2; i += 1024) d[i] = g_csr4[i];
    }

    // ---- phase 1b: stage input tile [row][c][x] ----
#pragma unroll
    for (int t = 0; t < 7; t++) {
        int p = warpId + (t << 5);
        if (p < ROWS * XT) {
            int rr = p / XT;
            int xx = p - rr * XT;
            int iy = y0 + rr;
            int ix = x0 + xx;
            float* sb = s_in + (rr * C + lane) * XP + xx;
            if ((iy < H) && (ix < W)) {
                const float* gb = in + (((bz * H + iy) * W + ix) * C) + lane;
                float v[8];
#pragma unroll
                for (int cg = 0; cg < 8; cg++) v[cg] = gb[cg * 32];
#pragma unroll
                for (int cg = 0; cg < 8; cg++) sb[cg * 32 * XP] = v[cg];
            } else {
#pragma unroll
                for (int cg = 0; cg < 8; cg++) sb[cg * 32 * XP] = 0.0f;
            }
        }
    }
    __syncthreads();

    // ---- phase 2: gather-accumulate, 8 o per warp, lane = x ----
    // software-pipelined: next CSR pair prefetched while current computes,
    // all data LDS batched ahead of the FMAs.
    const int oBase = warpId * 8;
    const float* s_in_lane = s_in + lane;
    float acc[8][TH];
#pragma unroll
    for (int oo = 0; oo < 8; oo++)
#pragma unroll
        for (int r = 0; r < TH; r++) acc[oo][r] = 0.0f;

#pragma unroll
    for (int oo = 0; oo < 8; oo++) {
        int k        = s_off[oBase + oo];
        const int k1 = s_off[oBase + oo + 1];
        if (k >= k1) continue;
        uint4 e = *(const uint4*)(s_csr + k);       // first pair
        for (; k + 2 < k1; k += 2) {
            uint4 en = *(const uint4*)(s_csr + k + 2);   // prefetch next pair
            const float* a0 = s_in_lane + e.x;
            const float* a1 = s_in_lane + e.z;
            float d0[TH], d1[TH];
#pragma unroll
            for (int r = 0; r < TH; r++) d0[r] = a0[r * RPITCH];
#pragma unroll
            for (int r = 0; r < TH; r++) d1[r] = a1[r * RPITCH];
            const float v0 = __uint_as_float(e.y);
            const float v1 = __uint_as_float(e.w);
#pragma unroll
            for (int r = 0; r < TH; r++) acc[oo][r] = fmaf(v0, d0[r], acc[oo][r]);
#pragma unroll
            for (int r = 0; r < TH; r++) acc[oo][r] = fmaf(v1, d1[r], acc[oo][r]);
            e = en;
        }
        {   // tail pair
            const float* a0 = s_in_lane + e.x;
            const float* a1 = s_in_lane + e.z;
            float d0[TH], d1[TH];
#pragma unroll
            for (int r = 0; r < TH; r++) d0[r] = a0[r * RPITCH];
#pragma unroll
            for (int r = 0; r < TH; r++) d1[r] = a1[r * RPITCH];
            const float v0 = __uint_as_float(e.y);
            const float v1 = __uint_as_float(e.w);
#pragma unroll
            for (int r = 0; r < TH; r++) acc[oo][r] = fmaf(v0, d0[r], acc[oo][r]);
#pragma unroll
            for (int r = 0; r < TH; r++) acc[oo][r] = fmaf(v1, d1[r], acc[oo][r]);
        }
    }
    __syncthreads();   // s_in dead -> reuse

    // ---- phase 3: transpose-stage and coalesced store ----
    float* s_out = s_in;  // [r][o][x], pitch TWP=33
#pragma unroll
    for (int oo = 0; oo < 8; oo++) {
        int o = oBase + oo;
#pragma unroll
        for (int r = 0; r < TH; r++)
            s_out[(r * O + o) * TWP + lane] = acc[oo][r];
    }
    __syncthreads();

    const int och  = tid & 255;
    const int pgrp = tid >> 8;             // 0..3
    const int obase32 = ((bz * OH + y0) * OW + x0) * O + och;
#pragma unroll
    for (int i = 0; i < 32; i++) {
        int p  = pgrp + (i << 2);          // 0..127
        int r  = p >> 5;
        int xx = p & 31;
        int gy = y0 + r;
        int gx = x0 + xx;
        if (gy < OH && gx < OW)
            out[obase32 + (r * OW + xx) * O] =
                s_out[(r * O + och) * TWP + xx];
    }
}

// ============================================================
extern "C" void kernel_launch(void* const* d_in, const int* in_sizes, int n_in,
                              void* d_out, int out_size)
{
    const float* in  = (const float*)d_in[0];
    const int*   wi  = (const int*)d_in[1];
    const float* wv  = (const float*)d_in[2];
    float*       out = (float*)d_out;

    int nnz = in_sizes[2];
    if (nnz > NNZ_CAP) nnz = NNZ_CAP;
    int B = in_sizes[0] / (H * W * C);

    prep_kernel<<<1, 1024>>>(wi, wv, nnz);

    cudaFuncSetAttribute(sparse_conv_kernel,
                         cudaFuncAttributeMaxDynamicSharedMemorySize, SMEM_BYTES);

    dim3 grid((OW + TW - 1) / TW, (OH + TH - 1) / TH, B);
    sparse_conv_kernel<<<grid, 1024, SMEM_BYTES>>>(in, out);
}